// round 2
// baseline (speedup 1.0000x reference)
#include <cuda_runtime.h>
#include <cuda_bf16.h>
#include <stdint.h>

#define NUM_SEGMENTS 4480
#define ATOM_DIM 64
#define BOND_DIM 16
#define N_EDGES 65536
#define NCOLS 1088   // 16*64 kernel-projected cols + 64 bias cols

// Scratch: per-atom projected features Y[a][c], c = k*64+i for c<1024, bias-proj for c>=1024
__device__ float g_Y[(size_t)NUM_SEGMENTS * NCOLS];

// ---------------------------------------------------------------------------
// Phase 1: Y = atom_feat (4480x64) @ W (64x1088)
//   W[j][k*64+i]   = kernel[k*4096 + i*64 + j]
//   W[j][1024 + i] = bias[i*64 + j]
// Tiled 64x64 fp32 GEMM, K=64 single pass.
// ---------------------------------------------------------------------------
__global__ void __launch_bounds__(256, 6)
proj_kernel(const float* __restrict__ atom,
            const float* __restrict__ kern,
            const float* __restrict__ bias)
{
    __shared__ float As[64][65];
    __shared__ float Ws[64][65];

    const int a0 = blockIdx.x * 64;   // 70 blocks, 4480 = 70*64 exact
    const int c0 = blockIdx.y * 64;   // 17 blocks, 1088 = 17*64 exact
    const int tid = threadIdx.x;

    // Load A tile (64x64), coalesced
    #pragma unroll
    for (int t = 0; t < 16; t++) {
        int idx = tid + t * 256;
        int r = idx >> 6, j = idx & 63;
        As[r][j] = atom[(a0 + r) * 64 + j];
    }
    // Load W tile as Ws[j][cc]; gmem contiguous in j (coalesced)
    #pragma unroll
    for (int t = 0; t < 16; t++) {
        int idx = tid + t * 256;
        int j = idx & 63, cc = idx >> 6;
        int c = c0 + cc;
        float w;
        if (c < 1024) {
            int k = c >> 6, i = c & 63;
            w = kern[k * 4096 + i * 64 + j];
        } else {
            w = bias[(c - 1024) * 64 + j];
        }
        Ws[j][cc] = w;
    }
    __syncthreads();

    const int tx = tid & 15;   // col group
    const int ty = tid >> 4;   // row group
    float acc[4][4] = {};

    #pragma unroll
    for (int k = 0; k < 64; k++) {
        float av[4], wv[4];
        #pragma unroll
        for (int r = 0; r < 4; r++) av[r] = As[ty * 4 + r][k];
        #pragma unroll
        for (int c = 0; c < 4; c++) wv[c] = Ws[k][tx * 4 + c];
        #pragma unroll
        for (int r = 0; r < 4; r++)
            #pragma unroll
            for (int c = 0; c < 4; c++)
                acc[r][c] = fmaf(av[r], wv[c], acc[r][c]);
    }

    #pragma unroll
    for (int r = 0; r < 4; r++) {
        size_t row = (size_t)(a0 + ty * 4 + r);
        #pragma unroll
        for (int c = 0; c < 4; c++)
            g_Y[row * NCOLS + (c0 + tx * 4 + c)] = acc[r][c];
    }
}

// ---------------------------------------------------------------------------
// Phase 2: per-edge combine + scatter.
//   msg_e[i] = Y[src][1024+i] + sum_k b_e[k] * Y[src][k*64+i]
//   atomicAdd(out[dst][i], msg_e[i])
// One warp per edge; lane handles i = lane and lane+32.
// pair is int32 [E,2] (JAX demotes int64 -> int32 without x64 mode).
// ---------------------------------------------------------------------------
__global__ void __launch_bounds__(256)
edge_kernel(const float* __restrict__ bond,
            const int* __restrict__ pair,
            float* __restrict__ out)
{
    int e = blockIdx.x * 8 + (threadIdx.x >> 5);
    if (e >= N_EDGES) return;
    const int lane = threadIdx.x & 31;

    int dst = pair[2 * e];
    int src = pair[2 * e + 1];

    // lanes 0..15 hold b[0..15], lanes 16..31 mirror them
    float bv = __ldg(&bond[(size_t)e * 16 + (lane & 15)]);

    const float* __restrict__ y = g_Y + (size_t)src * NCOLS;

    float m0 = y[1024 + lane];
    float m1 = y[1024 + 32 + lane];

    #pragma unroll
    for (int k = 0; k < 16; k++) {
        float bk = __shfl_sync(0xffffffffu, bv, k);
        m0 = fmaf(bk, y[k * 64 + lane],      m0);
        m1 = fmaf(bk, y[k * 64 + 32 + lane], m1);
    }

    atomicAdd(&out[(size_t)dst * 64 + lane],      m0);
    atomicAdd(&out[(size_t)dst * 64 + 32 + lane], m1);
}

extern "C" void kernel_launch(void* const* d_in, const int* in_sizes, int n_in,
                              void* d_out, int out_size)
{
    const float* atom = (const float*)d_in[0];      // [4480, 64]
    const float* bond = (const float*)d_in[1];      // [65536, 16]
    const int*   pair = (const int*)d_in[2];        // [65536, 2] int32
    const float* kern = (const float*)d_in[3];      // [16, 4096]
    const float* bias = (const float*)d_in[4];      // [4096]
    float*       out  = (float*)d_out;              // [4480, 64]

    (void)in_sizes; (void)n_in;

    cudaMemsetAsync(out, 0, (size_t)out_size * sizeof(float), 0);

    dim3 grid1(NUM_SEGMENTS / 64, NCOLS / 64);  // (70, 17)
    proj_kernel<<<grid1, 256>>>(atom, kern, bias);

    edge_kernel<<<N_EDGES / 8, 256>>>(bond, pair, out);
}